// round 16
// baseline (speedup 1.0000x reference)
#include <cuda_runtime.h>
#include <cuda_fp16.h>
#include <float.h>
#include <stdint.h>
#include <string.h>

// VectorQuantizer: filter (fp16 hi-product GEMM + rigorous margin) -> refine
// (exact fp32 on ~10-20 candidates/row).
// Pass-1 bound: |d_hi - d_true| <= m_r = 2^-9 * ||x_r|| * max_k ||e_k||.
// R16: TILE_M=128 (one 512-thread CTA/SM) halves codebook L2 re-streaming
// (the measured ~1540 cyc/chunk L2 cost vs 1920 cyc compute); 3-stage
// cp.async ring (wait_group 1) takes the load burst off the critical path.

#define DD      256
#define NMAX    32768
#define KMAX    8192
#define CAP     64

#define TILE_M  128
#define TILE_NC 256
#define BD      64
#define NT      512               // 16 warps: 4 (M) x 4 (N), 32x64 warp tiles

#define XSTRIDE       264          // fp16 per x row (256 + 8 pad)
#define ESTRIDE       72           // fp16 per e row (64 + 8 pad)
#define XBYTES        (TILE_M * XSTRIDE * 2)    // 67584
#define EBUF_BYTES    (TILE_NC * ESTRIDE * 2)   // 36864
#define SM_E          XBYTES
#define NSTAGE        3
#define SMEM_BYTES    (SM_E + NSTAGE * EBUF_BYTES)   // 178176

#define DOFF    16384.0f

__device__ float  g_esq[KMAX];
__device__ float  g_xsq[NMAX];
__device__ float  g_esqmax;
__device__ int    g_count[NMAX];
__device__ int    g_cand[(size_t)NMAX * CAP];
__device__ __half g_xh[(size_t)NMAX * DD];
__device__ __half g_eh[(size_t)KMAX * DD];

// ---------------------------------------------------------------------------
// helpers
// ---------------------------------------------------------------------------
__device__ __forceinline__ uint32_t smem_u32(const void* p) {
    uint32_t a;
    asm("{ .reg .u64 t; cvta.to.shared.u64 t, %1; cvt.u32.u64 %0, t; }"
        : "=r"(a) : "l"(p));
    return a;
}
__device__ __forceinline__ uint32_t h2_bits(__half2 h) {
    uint32_t u;
    memcpy(&u, &h, 4);
    return u;
}
__device__ __forceinline__ void ldsm_x4(uint32_t* r, uint32_t addr) {
    asm volatile("ldmatrix.sync.aligned.m8n8.x4.shared.b16 {%0,%1,%2,%3}, [%4];"
                 : "=r"(r[0]), "=r"(r[1]), "=r"(r[2]), "=r"(r[3]) : "r"(addr));
}
__device__ __forceinline__ void mma_f32acc(float* d, const uint32_t* a, uint32_t b0, uint32_t b1) {
    asm volatile(
        "mma.sync.aligned.m16n8k16.row.col.f32.f16.f16.f32 "
        "{%0,%1,%2,%3}, {%4,%5,%6,%7}, {%8,%9}, {%0,%1,%2,%3};"
        : "+f"(d[0]), "+f"(d[1]), "+f"(d[2]), "+f"(d[3])
        : "r"(a[0]), "r"(a[1]), "r"(a[2]), "r"(a[3]), "r"(b0), "r"(b1));
}
__device__ __forceinline__ void cp16(uint32_t dst, const void* src) {
    asm volatile("cp.async.cg.shared.global [%0], [%1], 16;"
                 :: "r"(dst), "l"(__cvta_generic_to_global(src)) : "memory");
}

// ---------------------------------------------------------------------------
// fused preprocessing: one warp per row -> fp16 copy + squared norm
// ---------------------------------------------------------------------------
__global__ void zmax_kernel() { g_esqmax = 0.0f; }

__global__ void prep_kernel(const float* __restrict__ src,
                            __half* __restrict__ dst,
                            float* __restrict__ sq,
                            int rows, int mode /*0=x (zero count), 1=e (max)*/) {
    int w    = (blockIdx.x * blockDim.x + threadIdx.x) >> 5;
    int lane = threadIdx.x & 31;
    if (w >= rows) return;
    const float4* p = (const float4*)(src + (size_t)w * DD + lane * 8);
    float4 a = p[0], b = p[1];
    float s = a.x*a.x + a.y*a.y + a.z*a.z + a.w*a.w
            + b.x*b.x + b.y*b.y + b.z*b.z + b.w*b.w;
#pragma unroll
    for (int off = 16; off > 0; off >>= 1)
        s += __shfl_xor_sync(0xffffffffu, s, off);

    uint4 hv;
    hv.x = h2_bits(__floats2half2_rn(a.x, a.y));
    hv.y = h2_bits(__floats2half2_rn(a.z, a.w));
    hv.z = h2_bits(__floats2half2_rn(b.x, b.y));
    hv.w = h2_bits(__floats2half2_rn(b.z, b.w));
    *(uint4*)(dst + (size_t)w * DD + lane * 8) = hv;

    if (lane == 0) {
        sq[w] = s;
        if (mode == 0) g_count[w] = 0;
        else           atomicMax((int*)&g_esqmax, __float_as_int(s));  // s >= 0
    }
}

// ---------------------------------------------------------------------------
// Pass 1: hi-product GEMM + candidate collection
// 16 warps, 1 CTA/SM, 3-stage cp.async ring, stale-gate collection.
// ---------------------------------------------------------------------------
__global__ __launch_bounds__(NT, 1)
void vq_filter_kernel(int N, int K) {
    extern __shared__ __align__(128) char smem[];
    __shared__ unsigned int s_gate[TILE_M];
    __shared__ float        s_thradd[TILE_M];

    const int tid  = threadIdx.x;
    const int wid  = tid >> 5;
    const int lane = tid & 31;
    const int gr   = lane >> 2;
    const int tc   = lane & 3;
    const int mw   = wid >> 2;        // 0..3 (M slice: mw*32)
    const int nw   = wid & 3;         // 0..3 (N slice: nw*64)
    const int row0 = blockIdx.x * TILE_M;

    const uint32_t smb = smem_u32(smem);
    const uint32_t smX = smb;
    const uint32_t smE = smb + SM_E;

    if (tid < TILE_M) {
        s_gate[tid] = 0xFFFFFFFFu;
        float m = 0.001953125f * sqrtf(g_xsq[row0 + tid] * g_esqmax);  // 2^-9
        s_thradd[tid] = 2.0f * m + 0.125f;
    }

    // resident x_hi tile: 128 rows x 512 B
    {
        const uint4* xh4 = (const uint4*)g_xh;
#pragma unroll
        for (int t = 0; t < 8; t++) {
            int idx = tid + t * NT;          // 0..4095
            int r   = idx >> 5;
            int g16 = idx & 31;
            size_t g = (size_t)(row0 + r) * 32 + g16;
            *(uint4*)(smem + (uint32_t)r * (XSTRIDE * 2) + (uint32_t)g16 * 16) = xh4[g];
        }
    }

    const uint32_t a_lane = (uint32_t)(lane & 15) * (XSTRIDE * 2) + (uint32_t)(lane & 16);
    const uint32_t b_lane = ((uint32_t)((lane & 7) + ((lane & 16) >> 1))) * (ESTRIDE * 2)
                          + (uint32_t)((lane & 8) << 1);

    const int n_tiles = K / TILE_NC;          // 32
    const int G       = n_tiles * (DD / BD);  // 128

    float acc[2][8][4];                       // 32x64 warp tile

    auto issue_load = [&](int g) {
        int c   = g & 3;
        int kt0 = (g >> 2) * TILE_NC;
        uint32_t dbase = smE + (uint32_t)(g % NSTAGE) * EBUF_BYTES;
#pragma unroll
        for (int t = 0; t < 4; t++) {
            int idx = tid + t * NT;          // 0..2047
            int j   = idx >> 3;              // code row 0..255
            int g16 = idx & 7;
            const __half* src = g_eh + (size_t)(kt0 + j) * DD + c * BD + g16 * 8;
            cp16(dbase + (uint32_t)j * (ESTRIDE * 2) + (uint32_t)g16 * 16, src);
        }
        asm volatile("cp.async.commit_group;" ::: "memory");
    };

    issue_load(0);
    issue_load(1);

    for (int g = 0; g < G; g++) {
        const int c   = g & 3;
        const int kt0 = (g >> 2) * TILE_NC;

        // loads issued so far: 0..g+1; allow 1 incomplete -> group g is done
        asm volatile("cp.async.wait_group 1;" ::: "memory");
        // single barrier: publishes buffer g; releases buffer (g-1)%NSTAGE
        // (its reads all happened between the previous barrier and this one;
        // the next write to that slot is load g+2, issued after this barrier).
        __syncthreads();
        if (g + 2 < G) issue_load(g + 2);   // overlaps compute below

        if (c == 0) {
#pragma unroll
            for (int mt = 0; mt < 2; mt++)
#pragma unroll
                for (int n = 0; n < 8; n++)
#pragma unroll
                    for (int v = 0; v < 4; v++) acc[mt][n][v] = 0.0f;
        }

        const uint32_t eb = smE + (uint32_t)(g % NSTAGE) * EBUF_BYTES;

#pragma unroll
        for (int ks = 0; ks < 4; ks++) {
            uint32_t ah[2][4];
#pragma unroll
            for (int mt = 0; mt < 2; mt++)
                ldsm_x4(ah[mt], smX + a_lane
                        + (uint32_t)(mw * 32 + mt * 16) * (XSTRIDE * 2)
                        + (uint32_t)(c * BD + ks * 16) * 2);
            uint32_t bh[4][4];
#pragma unroll
            for (int np = 0; np < 4; np++)
                ldsm_x4(bh[np], eb + b_lane
                        + (uint32_t)(nw * 64 + np * 16) * (ESTRIDE * 2)
                        + (uint32_t)(ks * 16) * 2);
#pragma unroll
            for (int mt = 0; mt < 2; mt++)
#pragma unroll
                for (int n = 0; n < 8; n++)
                    mma_f32acc(acc[mt][n], ah[mt], bh[n >> 1][(n & 1) * 2],
                               bh[n >> 1][(n & 1) * 2 + 1]);
        }

        // ---- tile epilogue: gate update + stale-gate collection (no sync).
        // Stale (larger) gates are conservative: d_q(k*) <= any_prefix_gate+2m,
        // so the true argmin is always collected.
        if (c == 3) {
            const int kb = kt0 + nw * 64;
#pragma unroll
            for (int mt = 0; mt < 2; mt++) {
                int r0 = mw * 32 + mt * 16 + gr;
                float dv[8][4];
                float mn0 = FLT_MAX, mn1 = FLT_MAX;
#pragma unroll
                for (int n = 0; n < 8; n++) {
                    const int c0 = kb + n * 8 + 2 * tc;
                    float2 es = *(const float2*)&g_esq[c0];
                    dv[n][0] = fmaf(-2.0f, acc[mt][n][0], es.x);
                    dv[n][1] = fmaf(-2.0f, acc[mt][n][1], es.y);
                    dv[n][2] = fmaf(-2.0f, acc[mt][n][2], es.x);
                    dv[n][3] = fmaf(-2.0f, acc[mt][n][3], es.y);
                    mn0 = fminf(mn0, fminf(dv[n][0], dv[n][1]));
                    mn1 = fminf(mn1, fminf(dv[n][2], dv[n][3]));
                }
                atomicMin(&s_gate[r0],     __float_as_uint(mn0 + DOFF));
                atomicMin(&s_gate[r0 + 8], __float_as_uint(mn1 + DOFF));
                float thr0 = __uint_as_float(s_gate[r0])     - DOFF + s_thradd[r0];
                float thr1 = __uint_as_float(s_gate[r0 + 8]) - DOFF + s_thradd[r0 + 8];
#pragma unroll
                for (int n = 0; n < 8; n++) {
                    const int c0 = kb + n * 8 + 2 * tc;
                    if (dv[n][0] < thr0) {
                        int p = atomicAdd(&g_count[row0 + r0], 1);
                        if (p < CAP) g_cand[(size_t)(row0 + r0) * CAP + p] = c0;
                    }
                    if (dv[n][1] < thr0) {
                        int p = atomicAdd(&g_count[row0 + r0], 1);
                        if (p < CAP) g_cand[(size_t)(row0 + r0) * CAP + p] = c0 + 1;
                    }
                    if (dv[n][2] < thr1) {
                        int p = atomicAdd(&g_count[row0 + r0 + 8], 1);
                        if (p < CAP) g_cand[(size_t)(row0 + r0 + 8) * CAP + p] = c0;
                    }
                    if (dv[n][3] < thr1) {
                        int p = atomicAdd(&g_count[row0 + r0 + 8], 1);
                        if (p < CAP) g_cand[(size_t)(row0 + r0 + 8) * CAP + p] = c0 + 1;
                    }
                }
            }
        }
    }
}

// ---------------------------------------------------------------------------
// Pass 2: exact fp32 refine over candidates (one warp per row)
// ---------------------------------------------------------------------------
__global__ __launch_bounds__(256)
void refine_kernel(const float* __restrict__ x, const float* __restrict__ e,
                   float* __restrict__ out, int N, int K) {
    int w    = (blockIdx.x * blockDim.x + threadIdx.x) >> 5;
    int lane = threadIdx.x & 31;
    if (w >= N) return;

    float xr[8];
    {
        const float4* p = (const float4*)(x + (size_t)w * DD + lane * 8);
        float4 a = p[0], b = p[1];
        xr[0]=a.x; xr[1]=a.y; xr[2]=a.z; xr[3]=a.w;
        xr[4]=b.x; xr[5]=b.y; xr[6]=b.z; xr[7]=b.w;
    }

    int cnt = g_count[w];
    float bd = FLT_MAX;
    int   bi = 0x7FFFFFFF;

    auto eval = [&](int k) {
        const float4* p = (const float4*)(e + (size_t)k * DD + lane * 8);
        float4 a = p[0], b = p[1];
        float s = xr[0]*a.x + xr[1]*a.y + xr[2]*a.z + xr[3]*a.w
                + xr[4]*b.x + xr[5]*b.y + xr[6]*b.z + xr[7]*b.w;
#pragma unroll
        for (int off = 16; off > 0; off >>= 1)
            s += __shfl_xor_sync(0xffffffffu, s, off);
        float d = fmaf(-2.0f, s, g_esq[k]);
        if (d < bd || (d == bd && k < bi)) { bd = d; bi = k; }
    };

    if (cnt >= CAP) {
        for (int k = 0; k < K; k++) eval(k);
    } else {
        for (int i = 0; i < cnt; i++) eval(g_cand[(size_t)w * CAP + i]);
    }
    if (lane == 0) out[w] = (float)bi;
}

// ---------------------------------------------------------------------------
// launch
// ---------------------------------------------------------------------------
extern "C" void kernel_launch(void* const* d_in, const int* in_sizes, int n_in,
                              void* d_out, int out_size) {
    const float* x;
    const float* e;
    int N, K;
    if (in_sizes[0] >= in_sizes[1]) {
        x = (const float*)d_in[0]; N = in_sizes[0] / DD;
        e = (const float*)d_in[1]; K = in_sizes[1] / DD;
    } else {
        x = (const float*)d_in[1]; N = in_sizes[1] / DD;
        e = (const float*)d_in[0]; K = in_sizes[0] / DD;
    }
    float* out = (float*)d_out;

    float *esq, *xsq;
    __half *xh, *eh;
    cudaGetSymbolAddress((void**)&esq, g_esq);
    cudaGetSymbolAddress((void**)&xsq, g_xsq);
    cudaGetSymbolAddress((void**)&xh,  g_xh);
    cudaGetSymbolAddress((void**)&eh,  g_eh);

    zmax_kernel<<<1, 1>>>();
    prep_kernel<<<(K * 32 + 255) / 256, 256>>>(e, eh, esq, K, 1);
    prep_kernel<<<(N * 32 + 255) / 256, 256>>>(x, xh, xsq, N, 0);

    cudaFuncSetAttribute(vq_filter_kernel,
                         cudaFuncAttributeMaxDynamicSharedMemorySize, SMEM_BYTES);
    vq_filter_kernel<<<N / TILE_M, NT, SMEM_BYTES>>>(N, K);
    refine_kernel<<<(N * 32 + 255) / 256, 256>>>(x, e, out, N, K);
}

// round 17
// speedup vs baseline: 1.0665x; 1.0665x over previous
#include <cuda_runtime.h>
#include <cuda_fp16.h>
#include <float.h>
#include <stdint.h>
#include <string.h>

// VectorQuantizer: filter (fp16 hi-product GEMM + rigorous margin) -> refine
// (exact fp32 on ~10-20 candidates/row).
// Pass-1 bound: |d_hi - d_true| <= m_r = 2^-9 * ||x_r|| * max_k ||e_k||.
// R17: epilogue cost surgery — smem candidate buffers (ATOMS not ATOMG),
// half-tile dv (16 regs), tile-0 min-only seed pass. Math identical to R15.

#define DD      256
#define NMAX    32768
#define KMAX    8192
#define CAP     64                 // global candidate slots per row
#define CAPS    16                 // smem candidate slots per row

#define TILE_M  64
#define TILE_NC 256
#define BD      64
#define NT      256               // 8 warps: 2 (M) x 4 (N), 32x64 warp tiles

#define XSTRIDE       264          // fp16 per x row (256 + 8 pad)
#define ESTRIDE       72           // fp16 per e row (64 + 8 pad)
#define XBYTES        (TILE_M * XSTRIDE * 2)    // 33792
#define EBUF_BYTES    (TILE_NC * ESTRIDE * 2)   // 36864
#define SM_E          XBYTES
#define SMEM_BYTES    (SM_E + 2 * EBUF_BYTES)   // 107520

#define DOFF    16384.0f

__device__ float  g_esq[KMAX];
__device__ float  g_xsq[NMAX];
__device__ float  g_esqmax;
__device__ int    g_count[NMAX];
__device__ int    g_cand[(size_t)NMAX * CAP];
__device__ __half g_xh[(size_t)NMAX * DD];
__device__ __half g_eh[(size_t)KMAX * DD];

// ---------------------------------------------------------------------------
// helpers
// ---------------------------------------------------------------------------
__device__ __forceinline__ uint32_t smem_u32(const void* p) {
    uint32_t a;
    asm("{ .reg .u64 t; cvta.to.shared.u64 t, %1; cvt.u32.u64 %0, t; }"
        : "=r"(a) : "l"(p));
    return a;
}
__device__ __forceinline__ uint32_t h2_bits(__half2 h) {
    uint32_t u;
    memcpy(&u, &h, 4);
    return u;
}
__device__ __forceinline__ void ldsm_x4(uint32_t* r, uint32_t addr) {
    asm volatile("ldmatrix.sync.aligned.m8n8.x4.shared.b16 {%0,%1,%2,%3}, [%4];"
                 : "=r"(r[0]), "=r"(r[1]), "=r"(r[2]), "=r"(r[3]) : "r"(addr));
}
__device__ __forceinline__ void mma_f32acc(float* d, const uint32_t* a, uint32_t b0, uint32_t b1) {
    asm volatile(
        "mma.sync.aligned.m16n8k16.row.col.f32.f16.f16.f32 "
        "{%0,%1,%2,%3}, {%4,%5,%6,%7}, {%8,%9}, {%0,%1,%2,%3};"
        : "+f"(d[0]), "+f"(d[1]), "+f"(d[2]), "+f"(d[3])
        : "r"(a[0]), "r"(a[1]), "r"(a[2]), "r"(a[3]), "r"(b0), "r"(b1));
}
__device__ __forceinline__ void cp16(uint32_t dst, const void* src) {
    asm volatile("cp.async.cg.shared.global [%0], [%1], 16;"
                 :: "r"(dst), "l"(__cvta_generic_to_global(src)) : "memory");
}

// ---------------------------------------------------------------------------
// fused preprocessing: one warp per row -> fp16 copy + squared norm
// ---------------------------------------------------------------------------
__global__ void zmax_kernel() { g_esqmax = 0.0f; }

__global__ void prep_kernel(const float* __restrict__ src,
                            __half* __restrict__ dst,
                            float* __restrict__ sq,
                            int rows, int mode /*0=x (zero count), 1=e (max)*/) {
    int w    = (blockIdx.x * blockDim.x + threadIdx.x) >> 5;
    int lane = threadIdx.x & 31;
    if (w >= rows) return;
    const float4* p = (const float4*)(src + (size_t)w * DD + lane * 8);
    float4 a = p[0], b = p[1];
    float s = a.x*a.x + a.y*a.y + a.z*a.z + a.w*a.w
            + b.x*b.x + b.y*b.y + b.z*b.z + b.w*b.w;
#pragma unroll
    for (int off = 16; off > 0; off >>= 1)
        s += __shfl_xor_sync(0xffffffffu, s, off);

    uint4 hv;
    hv.x = h2_bits(__floats2half2_rn(a.x, a.y));
    hv.y = h2_bits(__floats2half2_rn(a.z, a.w));
    hv.z = h2_bits(__floats2half2_rn(b.x, b.y));
    hv.w = h2_bits(__floats2half2_rn(b.z, b.w));
    *(uint4*)(dst + (size_t)w * DD + lane * 8) = hv;

    if (lane == 0) {
        sq[w] = s;
        if (mode == 0) g_count[w] = 0;
        else           atomicMax((int*)&g_esqmax, __float_as_int(s));  // s >= 0
    }
}

// ---------------------------------------------------------------------------
// Pass 1: hi-product GEMM + candidate collection (smem-buffered)
// ---------------------------------------------------------------------------
__global__ __launch_bounds__(NT, 2)
void vq_filter_kernel(int N, int K) {
    extern __shared__ __align__(128) char smem[];
    __shared__ unsigned int s_gate[TILE_M];
    __shared__ float        s_thradd[TILE_M];
    __shared__ int          s_cnt[TILE_M];
    __shared__ int          s_cand[TILE_M][CAPS];

    const int tid  = threadIdx.x;
    const int wid  = tid >> 5;
    const int lane = tid & 31;
    const int gr   = lane >> 2;
    const int tc   = lane & 3;
    const int mw   = wid >> 2;        // 0..1 (M slice: mw*32)
    const int nw   = wid & 3;         // 0..3 (N slice: nw*64)
    const int row0 = blockIdx.x * TILE_M;

    const uint32_t smb = smem_u32(smem);
    const uint32_t smX = smb;
    const uint32_t smE = smb + SM_E;

    if (tid < TILE_M) {
        s_gate[tid] = 0xFFFFFFFFu;
        s_cnt[tid]  = 0;
        float m = 0.001953125f * sqrtf(g_xsq[row0 + tid] * g_esqmax);  // 2^-9
        s_thradd[tid] = 2.0f * m + 0.125f;
    }

    // resident x_hi tile
    {
        const uint4* xh4 = (const uint4*)g_xh;
#pragma unroll
        for (int t = 0; t < 8; t++) {
            int idx = tid + t * NT;
            int r   = idx >> 5;
            int g16 = idx & 31;
            size_t g = (size_t)(row0 + r) * 32 + g16;
            *(uint4*)(smem + (uint32_t)r * (XSTRIDE * 2) + (uint32_t)g16 * 16) = xh4[g];
        }
    }

    const uint32_t a_lane = (uint32_t)(lane & 15) * (XSTRIDE * 2) + (uint32_t)(lane & 16);
    const uint32_t b_lane = ((uint32_t)((lane & 7) + ((lane & 16) >> 1))) * (ESTRIDE * 2)
                          + (uint32_t)((lane & 8) << 1);

    const int n_tiles = K / TILE_NC;          // 32
    const int G       = n_tiles * (DD / BD);  // 128

    float acc[2][8][4];                       // 32x64 warp tile

    auto issue_load = [&](int g) {
        int c   = g & 3;
        int kt0 = (g >> 2) * TILE_NC;
        uint32_t dbase = smE + (uint32_t)(g & 1) * EBUF_BYTES;
#pragma unroll
        for (int t = 0; t < 8; t++) {
            int idx = tid + t * NT;          // 0..2047
            int j   = idx >> 3;              // code row 0..255
            int g16 = idx & 7;
            const __half* src = g_eh + (size_t)(kt0 + j) * DD + c * BD + g16 * 8;
            cp16(dbase + (uint32_t)j * (ESTRIDE * 2) + (uint32_t)g16 * 16, src);
        }
        asm volatile("cp.async.commit_group;" ::: "memory");
    };

    issue_load(0);

    for (int g = 0; g < G; g++) {
        const int c   = g & 3;
        const int kt  = g >> 2;
        const int kt0 = kt * TILE_NC;

        asm volatile("cp.async.wait_group 0;" ::: "memory");
        // single barrier: publishes buffer g, releases buffer g-1
        __syncthreads();
        if (g + 1 < G) issue_load(g + 1);   // overlaps compute below

        if (c == 0) {
#pragma unroll
            for (int mt = 0; mt < 2; mt++)
#pragma unroll
                for (int n = 0; n < 8; n++)
#pragma unroll
                    for (int v = 0; v < 4; v++) acc[mt][n][v] = 0.0f;
        }

        const uint32_t eb = smE + (uint32_t)(g & 1) * EBUF_BYTES;

#pragma unroll
        for (int ks = 0; ks < 4; ks++) {
            uint32_t ah[2][4];
#pragma unroll
            for (int mt = 0; mt < 2; mt++)
                ldsm_x4(ah[mt], smX + a_lane
                        + (uint32_t)(mw * 32 + mt * 16) * (XSTRIDE * 2)
                        + (uint32_t)(c * BD + ks * 16) * 2);
            uint32_t bh[4][4];
#pragma unroll
            for (int np = 0; np < 4; np++)
                ldsm_x4(bh[np], eb + b_lane
                        + (uint32_t)(nw * 64 + np * 16) * (ESTRIDE * 2)
                        + (uint32_t)(ks * 16) * 2);
#pragma unroll
            for (int mt = 0; mt < 2; mt++)
#pragma unroll
                for (int n = 0; n < 8; n++)
                    mma_f32acc(acc[mt][n], ah[mt], bh[n >> 1][(n & 1) * 2],
                               bh[n >> 1][(n & 1) * 2 + 1]);
        }

        // ---- tile epilogue ----
        if (c == 3) {
            const int kb = kt0 + nw * 64;

            // Tile 0: min-only seed pass + barrier, so collection thresholds
            // below always include a full-tile gate (prevents flood).
            if (kt == 0) {
#pragma unroll
                for (int mt = 0; mt < 2; mt++) {
                    float mn0 = FLT_MAX, mn1 = FLT_MAX;
#pragma unroll
                    for (int n = 0; n < 8; n++) {
                        const int c0 = kb + n * 8 + 2 * tc;
                        float esx = __ldg(&g_esq[c0]);
                        float esy = __ldg(&g_esq[c0 + 1]);
                        mn0 = fminf(mn0, fminf(fmaf(-2.0f, acc[mt][n][0], esx),
                                               fmaf(-2.0f, acc[mt][n][1], esy)));
                        mn1 = fminf(mn1, fminf(fmaf(-2.0f, acc[mt][n][2], esx),
                                               fmaf(-2.0f, acc[mt][n][3], esy)));
                    }
                    int r0 = mw * 32 + mt * 16 + gr;
                    atomicMin(&s_gate[r0],     __float_as_uint(mn0 + DOFF));
                    atomicMin(&s_gate[r0 + 8], __float_as_uint(mn1 + DOFF));
                }
                __syncthreads();
            }

            // Normal epilogue: two half-passes (dv = 16 regs), smem collection.
#pragma unroll
            for (int mt = 0; mt < 2; mt++) {
                const int r0 = mw * 32 + mt * 16 + gr;
#pragma unroll
                for (int h = 0; h < 2; h++) {
                    float dv[4][4];
                    float mn0 = FLT_MAX, mn1 = FLT_MAX;
#pragma unroll
                    for (int j = 0; j < 4; j++) {
                        const int n  = h * 4 + j;
                        const int c0 = kb + n * 8 + 2 * tc;
                        float esx = __ldg(&g_esq[c0]);
                        float esy = __ldg(&g_esq[c0 + 1]);
                        dv[j][0] = fmaf(-2.0f, acc[mt][n][0], esx);
                        dv[j][1] = fmaf(-2.0f, acc[mt][n][1], esy);
                        dv[j][2] = fmaf(-2.0f, acc[mt][n][2], esx);
                        dv[j][3] = fmaf(-2.0f, acc[mt][n][3], esy);
                        mn0 = fminf(mn0, fminf(dv[j][0], dv[j][1]));
                        mn1 = fminf(mn1, fminf(dv[j][2], dv[j][3]));
                    }
                    atomicMin(&s_gate[r0],     __float_as_uint(mn0 + DOFF));
                    atomicMin(&s_gate[r0 + 8], __float_as_uint(mn1 + DOFF));
                    float thr0 = __uint_as_float(s_gate[r0])     - DOFF + s_thradd[r0];
                    float thr1 = __uint_as_float(s_gate[r0 + 8]) - DOFF + s_thradd[r0 + 8];
#pragma unroll
                    for (int j = 0; j < 4; j++) {
                        const int n  = h * 4 + j;
                        const int c0 = kb + n * 8 + 2 * tc;
#pragma unroll
                        for (int v = 0; v < 4; v++) {
                            const int rr = (v < 2) ? r0 : r0 + 8;
                            const float thr = (v < 2) ? thr0 : thr1;
                            if (dv[j][v] < thr) {
                                int kk = c0 + (v & 1);
                                int p = atomicAdd(&s_cnt[rr], 1);
                                if (p < CAPS) {
                                    s_cand[rr][p] = kk;
                                } else {
                                    int q = atomicAdd(&g_count[row0 + rr], 1);
                                    if (q < CAP) g_cand[(size_t)(row0 + rr) * CAP + q] = kk;
                                }
                            }
                        }
                    }
                }
            }
        }
    }

    // ---- flush smem candidates to global ----
    __syncthreads();
    if (tid < TILE_M) {
        int r  = row0 + tid;
        int ns = min(s_cnt[tid], CAPS);
        int base = atomicAdd(&g_count[r], ns);
        for (int i = 0; i < ns; i++) {
            int q = base + i;
            if (q < CAP) g_cand[(size_t)r * CAP + q] = s_cand[tid][i];
            // if q >= CAP, g_count[r] > CAP already -> refine full-scan fallback
        }
    }
}

// ---------------------------------------------------------------------------
// Pass 2: exact fp32 refine over candidates (one warp per row)
// ---------------------------------------------------------------------------
__global__ __launch_bounds__(256)
void refine_kernel(const float* __restrict__ x, const float* __restrict__ e,
                   float* __restrict__ out, int N, int K) {
    int w    = (blockIdx.x * blockDim.x + threadIdx.x) >> 5;
    int lane = threadIdx.x & 31;
    if (w >= N) return;

    float xr[8];
    {
        const float4* p = (const float4*)(x + (size_t)w * DD + lane * 8);
        float4 a = p[0], b = p[1];
        xr[0]=a.x; xr[1]=a.y; xr[2]=a.z; xr[3]=a.w;
        xr[4]=b.x; xr[5]=b.y; xr[6]=b.z; xr[7]=b.w;
    }

    int cnt = g_count[w];
    float bd = FLT_MAX;
    int   bi = 0x7FFFFFFF;

    auto eval = [&](int k) {
        const float4* p = (const float4*)(e + (size_t)k * DD + lane * 8);
        float4 a = p[0], b = p[1];
        float s = xr[0]*a.x + xr[1]*a.y + xr[2]*a.z + xr[3]*a.w
                + xr[4]*b.x + xr[5]*b.y + xr[6]*b.z + xr[7]*b.w;
#pragma unroll
        for (int off = 16; off > 0; off >>= 1)
            s += __shfl_xor_sync(0xffffffffu, s, off);
        float d = fmaf(-2.0f, s, g_esq[k]);
        if (d < bd || (d == bd && k < bi)) { bd = d; bi = k; }
    };

    if (cnt >= CAP) {
        for (int k = 0; k < K; k++) eval(k);
    } else {
        for (int i = 0; i < cnt; i++) eval(g_cand[(size_t)w * CAP + i]);
    }
    if (lane == 0) out[w] = (float)bi;
}

// ---------------------------------------------------------------------------
// launch
// ---------------------------------------------------------------------------
extern "C" void kernel_launch(void* const* d_in, const int* in_sizes, int n_in,
                              void* d_out, int out_size) {
    const float* x;
    const float* e;
    int N, K;
    if (in_sizes[0] >= in_sizes[1]) {
        x = (const float*)d_in[0]; N = in_sizes[0] / DD;
        e = (const float*)d_in[1]; K = in_sizes[1] / DD;
    } else {
        x = (const float*)d_in[1]; N = in_sizes[1] / DD;
        e = (const float*)d_in[0]; K = in_sizes[0] / DD;
    }
    float* out = (float*)d_out;

    float *esq, *xsq;
    __half *xh, *eh;
    cudaGetSymbolAddress((void**)&esq, g_esq);
    cudaGetSymbolAddress((void**)&xsq, g_xsq);
    cudaGetSymbolAddress((void**)&xh,  g_xh);
    cudaGetSymbolAddress((void**)&eh,  g_eh);

    zmax_kernel<<<1, 1>>>();
    prep_kernel<<<(K * 32 + 255) / 256, 256>>>(e, eh, esq, K, 1);
    prep_kernel<<<(N * 32 + 255) / 256, 256>>>(x, xh, xsq, N, 0);

    cudaFuncSetAttribute(vq_filter_kernel,
                         cudaFuncAttributeMaxDynamicSharedMemorySize, SMEM_BYTES);
    vq_filter_kernel<<<N / TILE_M, NT, SMEM_BYTES>>>(N, K);
    refine_kernel<<<(N * 32 + 255) / 256, 256>>>(x, e, out, N, K);
}